// round 11
// baseline (speedup 1.0000x reference)
#include <cuda_runtime.h>
#include <cuda_bf16.h>
#include <math_constants.h>

// SelfContactSmall: vertices [B=2, N, 3] f32, geomask [N, N] (bool widened to i32).
// out = concat(v2v_min [B*N] f32, in_contact [B*N] as 0.0/1.0 f32)
//
// v2v_min[b][j] = min over i with geomask[i][j] of ||v[b][i] - v[b][j]||^2
// in_contact[b][j] = v2v_min[b][j] < 0.02^2

#define BATCH    2
#define THREADS  256
#define ROWTILE  128
#define ISPLITS  16
#define THRES2   0.0004f   // 0.02^2

// ---------------------------------------------------------------------------
// Kernel 1: init the v2v_min region of d_out to +inf (d_out is poisoned 0xAA).
// ---------------------------------------------------------------------------
__global__ void sc_init_kernel(int* __restrict__ out_bits, int n_total) {
    int i = blockIdx.x * blockDim.x + threadIdx.x;
    if (i < n_total) out_bits[i] = 0x7f800000;  // +inf as float bits
}

// ---------------------------------------------------------------------------
// Kernel 2: masked column-min of pairwise squared distances.
// grid.x = column tiles (THREADS cols each), grid.y = row splits.
// One thread owns one column j for BOTH batches (mask byte shared).
// Row vertices staged in SMEM as float4 -> 1 LDS.128 per batch per row.
// Partial mins merged via integer atomicMin (all values >= 0, so float-bit
// ordering == integer ordering).
// ---------------------------------------------------------------------------
__global__ __launch_bounds__(THREADS)
void sc_min_kernel(const float* __restrict__ verts,
                   const int*   __restrict__ gmask,
                   float*       __restrict__ out,
                   int N) {
    __shared__ float4 sv[BATCH][ROWTILE];

    const int j = blockIdx.x * THREADS + threadIdx.x;
    const bool valid = (j < N);

    const int chunk = (N + ISPLITS - 1) / ISPLITS;
    const int ibeg  = blockIdx.y * chunk;
    const int iend  = min(N, ibeg + chunk);

    // This column's vertex coords, both batches.
    float x0 = 0.f, y0 = 0.f, z0 = 0.f, x1 = 0.f, y1 = 0.f, z1 = 0.f;
    if (valid) {
        x0 = verts[j * 3 + 0];
        y0 = verts[j * 3 + 1];
        z0 = verts[j * 3 + 2];
        x1 = verts[(size_t)N * 3 + j * 3 + 0];
        y1 = verts[(size_t)N * 3 + j * 3 + 1];
        z1 = verts[(size_t)N * 3 + j * 3 + 2];
    }

    float m0 = CUDART_INF_F, m1 = CUDART_INF_F;

    float* s0 = reinterpret_cast<float*>(&sv[0][0]);
    float* s1 = reinterpret_cast<float*>(&sv[1][0]);

    for (int i0 = ibeg; i0 < iend; i0 += ROWTILE) {
        const int cnt = min(ROWTILE, iend - i0);

        __syncthreads();
        // Cooperative load of row-tile vertices into float4-strided SMEM
        // (x,y,z packed into .x/.y/.z of each float4; .w unused).
        for (int t = threadIdx.x; t < cnt * 3; t += THREADS) {
            const int r = t / 3;
            const int k = t - r * 3;
            s0[r * 4 + k] = verts[(size_t)(i0 + r) * 3 + k];
            s1[r * 4 + k] = verts[(size_t)N * 3 + (size_t)(i0 + r) * 3 + k];
        }
        __syncthreads();

        if (valid) {
            const int* gmrow = gmask + (size_t)i0 * N + j;
            #pragma unroll 4
            for (int r = 0; r < cnt; r++) {
                const int ok = gmrow[(size_t)r * N];

                const float4 a = sv[0][r];
                float dx = a.x - x0, dy = a.y - y0, dz = a.z - z0;
                const float d0 = fmaf(dz, dz, fmaf(dy, dy, dx * dx));

                const float4 b = sv[1][r];
                float ex = b.x - x1, ey = b.y - y1, ez = b.z - z1;
                const float d1 = fmaf(ez, ez, fmaf(ey, ey, ex * ex));

                if (ok) {
                    m0 = fminf(m0, d0);
                    m1 = fminf(m1, d1);
                }
            }
        }
    }

    if (valid) {
        atomicMin(reinterpret_cast<int*>(&out[j]),     __float_as_int(m0));
        atomicMin(reinterpret_cast<int*>(&out[N + j]), __float_as_int(m1));
    }
}

// ---------------------------------------------------------------------------
// Kernel 3: threshold the mins into the in_contact region (as 0.0/1.0 f32).
// ---------------------------------------------------------------------------
__global__ void sc_final_kernel(float* __restrict__ out, int n_total) {
    int i = blockIdx.x * blockDim.x + threadIdx.x;
    if (i < n_total) {
        out[n_total + i] = (out[i] < THRES2) ? 1.0f : 0.0f;
    }
}

// ---------------------------------------------------------------------------
extern "C" void kernel_launch(void* const* d_in, const int* in_sizes, int n_in,
                              void* d_out, int out_size) {
    const float* verts = (const float*)d_in[0];   // [B, N, 3] f32
    const int*   gmask = (const int*)d_in[1];     // [N, N] bool -> i32

    float* out = (float*)d_out;

    const int N = in_sizes[0] / (BATCH * 3);      // 10475
    const int n_total = BATCH * N;                // 20950

    // 1) init mins to +inf
    {
        int blocks = (n_total + THREADS - 1) / THREADS;
        sc_init_kernel<<<blocks, THREADS>>>((int*)out, n_total);
    }

    // 2) masked column-min
    {
        dim3 grid((N + THREADS - 1) / THREADS, ISPLITS);
        sc_min_kernel<<<grid, THREADS>>>(verts, gmask, out, N);
    }

    // 3) contact threshold
    {
        int blocks = (n_total + THREADS - 1) / THREADS;
        sc_final_kernel<<<blocks, THREADS>>>(out, n_total);
    }
}